// round 1
// baseline (speedup 1.0000x reference)
#include <cuda_runtime.h>
#include <math.h>

// ---------------------------------------------------------------------------
// SpatioTemporalAttention
//   x: [B=2, T=16, N=1024, D=256], H=8, dh=32
//   spatial MHA over N (batch B*T=32), temporal MHA over T (batch B*N=2048),
//   final projection p_w.
// Key insight: QKV projections are pointwise per token, so everything stays in
// the flat (b,t,n) token order; only the attention kernels care about grouping.
// ---------------------------------------------------------------------------

#define TOKENS 32768          // B*T*N
#define DMODEL 256
#define E3 768                // 3*D

// Scratch (device globals: allocation-free per harness rules)
__device__ float g_qkv[TOKENS * E3];      // 25.2M floats
__device__ float g_bufA[TOKENS * DMODEL]; // attention output
__device__ float g_bufB[TOKENS * DMODEL]; // projection output

// ---------------------------------------------------------------------------
// C[M,N] = A[M,K] * B[N,K]^T + bias[N]      (row-major A, row-major B)
// 128x128 tile, BK=16, 256 threads, 8x8 microtile.
// ---------------------------------------------------------------------------
__global__ void __launch_bounds__(256, 2)
sgemm_bias_nt(const float* __restrict__ A, const float* __restrict__ B,
              const float* __restrict__ bias, float* __restrict__ C,
              int M, int N, int K)
{
    __shared__ __align__(16) float As[16][132];
    __shared__ __align__(16) float Bs[16][132];

    const int tid = threadIdx.x;
    const int bm = blockIdx.y * 128;
    const int bn = blockIdx.x * 128;
    const int tx = tid & 15;   // n dir
    const int ty = tid >> 4;   // m dir

    float c[8][8];
#pragma unroll
    for (int i = 0; i < 8; i++)
#pragma unroll
        for (int j = 0; j < 8; j++) c[i][j] = 0.f;

    const int lr = tid >> 2;        // 0..63
    const int lc = (tid & 3) * 4;   // 0,4,8,12

    for (int kk = 0; kk < K; kk += 16) {
        __syncthreads();
#pragma unroll
        for (int i = 0; i < 2; i++) {
            int r = lr + i * 64;
            float4 av = *(const float4*)(A + (size_t)(bm + r) * K + kk + lc);
            float4 bv = *(const float4*)(B + (size_t)(bn + r) * K + kk + lc);
            As[lc + 0][r] = av.x; As[lc + 1][r] = av.y;
            As[lc + 2][r] = av.z; As[lc + 3][r] = av.w;
            Bs[lc + 0][r] = bv.x; Bs[lc + 1][r] = bv.y;
            Bs[lc + 2][r] = bv.z; Bs[lc + 3][r] = bv.w;
        }
        __syncthreads();
#pragma unroll
        for (int k = 0; k < 16; k++) {
            float4 a0 = *(const float4*)&As[k][ty * 8];
            float4 a1 = *(const float4*)&As[k][ty * 8 + 4];
            float4 b0 = *(const float4*)&Bs[k][tx * 8];
            float4 b1 = *(const float4*)&Bs[k][tx * 8 + 4];
            float a[8] = {a0.x, a0.y, a0.z, a0.w, a1.x, a1.y, a1.z, a1.w};
            float b[8] = {b0.x, b0.y, b0.z, b0.w, b1.x, b1.y, b1.z, b1.w};
#pragma unroll
            for (int i = 0; i < 8; i++)
#pragma unroll
                for (int j = 0; j < 8; j++)
                    c[i][j] += a[i] * b[j];
        }
    }

    float4 bia0 = *(const float4*)(bias + bn + tx * 8);
    float4 bia1 = *(const float4*)(bias + bn + tx * 8 + 4);
    const float bb[8] = {bia0.x, bia0.y, bia0.z, bia0.w,
                         bia1.x, bia1.y, bia1.z, bia1.w};
#pragma unroll
    for (int i = 0; i < 8; i++) {
        float* crow = C + (size_t)(bm + ty * 8 + i) * N + bn + tx * 8;
        float4 v0 = make_float4(c[i][0] + bb[0], c[i][1] + bb[1],
                                c[i][2] + bb[2], c[i][3] + bb[3]);
        float4 v1 = make_float4(c[i][4] + bb[4], c[i][5] + bb[5],
                                c[i][6] + bb[6], c[i][7] + bb[7]);
        *(float4*)crow = v0;
        *(float4*)(crow + 4) = v1;
    }
}

// ---------------------------------------------------------------------------
// Spatial attention: S=1024 per (b,t), H=8 heads, dh=32.
// Grid: (qblock=8, h=8, bt=32). 128 threads, 1 thread = 1 query row.
// qkv rows: token (b,t,n) -> row (b*T+t)*N+n, layout [q(256) k(256) v(256)].
// Output: bufA[row, h*32+d].
// ---------------------------------------------------------------------------
__global__ void __launch_bounds__(128)
spatial_attn(const float* __restrict__ qkv, float* __restrict__ out)
{
    const int S = 1024;
    const int tid = threadIdx.x;
    const int qb = blockIdx.x;
    const int h  = blockIdx.y;
    const int bt = blockIdx.z;
    const int qrow = bt * S + qb * 128 + tid;

    __shared__ __align__(16) float Ks[64][32];
    __shared__ __align__(16) float Vs[64][32];

    const float scale = 0.17677669529663687f; // 1/sqrt(32)
    float q[32];
    {
        const float* qptr = qkv + (size_t)qrow * E3 + h * 32;
#pragma unroll
        for (int d = 0; d < 32; d += 4) {
            float4 t = *(const float4*)(qptr + d);
            q[d] = t.x * scale; q[d + 1] = t.y * scale;
            q[d + 2] = t.z * scale; q[d + 3] = t.w * scale;
        }
    }
    float o[32];
#pragma unroll
    for (int d = 0; d < 32; d++) o[d] = 0.f;
    float m = -1e30f, l = 0.f;

    for (int kb = 0; kb < S; kb += 64) {
        __syncthreads();
#pragma unroll
        for (int i = 0; i < 4; i++) {
            int f = tid + i * 128;          // 0..511
            int r = f >> 3;                 // 0..63
            int cc = (f & 7) * 4;           // 0..28
            const float* base = qkv + (size_t)(bt * S + kb + r) * E3 + h * 32;
            *(float4*)&Ks[r][cc] = *(const float4*)(base + 256 + cc);
            *(float4*)&Vs[r][cc] = *(const float4*)(base + 512 + cc);
        }
        __syncthreads();

        float s[64];
#pragma unroll
        for (int j = 0; j < 64; j++) {
            const float4* kr = (const float4*)Ks[j];
            float acc = 0.f;
#pragma unroll
            for (int dq = 0; dq < 8; dq++) {
                float4 kv = kr[dq];
                acc += q[dq * 4 + 0] * kv.x + q[dq * 4 + 1] * kv.y +
                       q[dq * 4 + 2] * kv.z + q[dq * 4 + 3] * kv.w;
            }
            s[j] = acc;
        }
        float mt = m;
#pragma unroll
        for (int j = 0; j < 64; j++) mt = fmaxf(mt, s[j]);
        float corr = __expf(m - mt);
        m = mt;
        l *= corr;
#pragma unroll
        for (int d = 0; d < 32; d++) o[d] *= corr;
#pragma unroll
        for (int j = 0; j < 64; j++) {
            float p = __expf(s[j] - m);
            l += p;
            const float4* vr = (const float4*)Vs[j];
#pragma unroll
            for (int dq = 0; dq < 8; dq++) {
                float4 vv = vr[dq];
                o[dq * 4 + 0] += p * vv.x; o[dq * 4 + 1] += p * vv.y;
                o[dq * 4 + 2] += p * vv.z; o[dq * 4 + 3] += p * vv.w;
            }
        }
    }
    const float inv = 1.f / l;
    float* optr = out + (size_t)qrow * DMODEL + h * 32;
#pragma unroll
    for (int d = 0; d < 32; d += 4)
        *(float4*)(optr + d) = make_float4(o[d] * inv, o[d + 1] * inv,
                                           o[d + 2] * inv, o[d + 3] * inv);
}

// ---------------------------------------------------------------------------
// Temporal attention: T=16 per (b,n), H=8. Grid: 2048 CTAs, 128 threads.
// Thread (h, tq): h = tid>>4, tq = tid&15. Whole 16x768 slab in smem.
// ---------------------------------------------------------------------------
__global__ void __launch_bounds__(128)
temporal_attn(const float* __restrict__ qkv, float* __restrict__ out)
{
    const int T = 16, N = 1024;
    const int bid = blockIdx.x;
    const int b = bid >> 10;
    const int n = bid & 1023;
    const int tid = threadIdx.x;
    const int h  = tid >> 4;
    const int tq = tid & 15;

    __shared__ __align__(16) float sm[16][768]; // 48 KB

    for (int i = tid; i < 3072; i += 128) {     // 3072 float4
        int r = i / 192;
        int cc = (i % 192) * 4;
        size_t row = (size_t)(b * T + r) * N + n;
        *(float4*)&sm[r][cc] = *(const float4*)(qkv + row * E3 + cc);
    }
    __syncthreads();

    const float scale = 0.17677669529663687f;
    float q[32];
#pragma unroll
    for (int d = 0; d < 32; d++) q[d] = sm[tq][h * 32 + d] * scale;

    float s[16];
    float mx = -1e30f;
#pragma unroll
    for (int tk = 0; tk < 16; tk++) {
        float acc = 0.f;
#pragma unroll
        for (int d = 0; d < 32; d++)
            acc += q[d] * sm[tk][256 + h * 32 + d];
        s[tk] = acc;
        mx = fmaxf(mx, acc);
    }
    float l = 0.f;
#pragma unroll
    for (int tk = 0; tk < 16; tk++) { s[tk] = __expf(s[tk] - mx); l += s[tk]; }
    const float inv = 1.f / l;

    float o[32];
#pragma unroll
    for (int d = 0; d < 32; d++) o[d] = 0.f;
#pragma unroll
    for (int tk = 0; tk < 16; tk++) {
        float p = s[tk];
#pragma unroll
        for (int d = 0; d < 32; d++)
            o[d] += p * sm[tk][512 + h * 32 + d];
    }

    size_t orow = (size_t)(b * T + tq) * N + n;
    float* optr = out + orow * DMODEL + h * 32;
#pragma unroll
    for (int d = 0; d < 32; d += 4)
        *(float4*)(optr + d) = make_float4(o[d] * inv, o[d + 1] * inv,
                                           o[d + 2] * inv, o[d + 3] * inv);
}

// ---------------------------------------------------------------------------
extern "C" void kernel_launch(void* const* d_in, const int* in_sizes, int n_in,
                              void* d_out, int out_size)
{
    const float* x      = (const float*)d_in[0];
    const float* s_wqkv = (const float*)d_in[1];
    const float* s_bqkv = (const float*)d_in[2];
    const float* s_wo   = (const float*)d_in[3];
    const float* s_bo   = (const float*)d_in[4];
    const float* t_wqkv = (const float*)d_in[5];
    const float* t_bqkv = (const float*)d_in[6];
    const float* t_wo   = (const float*)d_in[7];
    const float* t_bo   = (const float*)d_in[8];
    const float* p_w    = (const float*)d_in[9];
    const float* p_b    = (const float*)d_in[10];
    float* out = (float*)d_out;

    void* p;
    cudaGetSymbolAddress(&p, g_qkv);  float* qkv  = (float*)p;
    cudaGetSymbolAddress(&p, g_bufA); float* bufA = (float*)p;
    cudaGetSymbolAddress(&p, g_bufB); float* bufB = (float*)p;

    // 1) spatial QKV projection (token-pointwise, flat layout)
    sgemm_bias_nt<<<dim3(6, 256), 256>>>(x, s_wqkv, s_bqkv, qkv, TOKENS, E3, DMODEL);
    // 2) spatial attention over N
    spatial_attn<<<dim3(8, 8, 32), 128>>>(qkv, bufA);
    // 3) spatial output projection
    sgemm_bias_nt<<<dim3(2, 256), 256>>>(bufA, s_wo, s_bo, bufB, TOKENS, DMODEL, DMODEL);
    // 4) temporal QKV projection
    sgemm_bias_nt<<<dim3(6, 256), 256>>>(bufB, t_wqkv, t_bqkv, qkv, TOKENS, E3, DMODEL);
    // 5) temporal attention over T
    temporal_attn<<<2048, 128>>>(qkv, bufA);
    // 6) temporal output projection
    sgemm_bias_nt<<<dim3(2, 256), 256>>>(bufA, t_wo, t_bo, bufB, TOKENS, DMODEL, DMODEL);
    // 7) final projection
    sgemm_bias_nt<<<dim3(2, 256), 256>>>(bufB, p_w, p_b, out, TOKENS, DMODEL, DMODEL);
}